// round 5
// baseline (speedup 1.0000x reference)
#include <cuda_runtime.h>
#include <math_constants.h>

#define TPB   256
#define MI    1024                     // interpolation cells
#define KMAX  1024
#define LOF   (-0.015625f)             // table domain start
#define HSTEP (33.0f/32768.0f)         // cell width h (exact in fp32)
#define INVH  (32768.0f/33.0f)         // 1/h
#define TT0   (512.0f/33.0f)           // -LOF/h

// Device scratch (no allocations allowed)
__device__ float4 g_params[KMAX];      // {mu, s=-0.5*inv_var*log2e, b=log2(coef), 0}
__device__ float  g_y[MI + 3];         // g_y[j] = prob(LOF + (j-1)*h), j in [0, MI+2]
__device__ float4 g_coef[MI];          // per-cell cubic {c0,c1,c2,c3} in local f
__device__ int    g_interp;            // 1 -> interpolation valid
__device__ float  g_mx, g_tot;         // softmax stats (K>KMAX ultra-fallback)

__device__ __forceinline__ float ex2(float a) {
    float r;
    asm("ex2.approx.f32 %0, %1;" : "=f"(r) : "f"(a));
    return r;
}

// ---------------------------------------------------------------------------
// Builder: softmax + param fold (redundantly per block); each thread evaluates
// ONE table grid point exactly (full K sum) into g_y. Block 0 publishes params.
// ---------------------------------------------------------------------------
__global__ void build_kernel(const float* __restrict__ pi_l,
                             const float* __restrict__ mu,
                             const float* __restrict__ lv, int K) {
    __shared__ float  sred[TPB];
    __shared__ float4 sp[KMAX];        // 16 KB
    int t = threadIdx.x;
    int kok = (K <= KMAX);

    // softmax max
    float m = -CUDART_INF_F;
    for (int k = t; k < K; k += TPB) m = fmaxf(m, pi_l[k]);
    sred[t] = m; __syncthreads();
    for (int s = TPB / 2; s > 0; s >>= 1) {
        if (t < s) sred[t] = fmaxf(sred[t], sred[t + s]);
        __syncthreads();
    }
    float mx = sred[0]; __syncthreads();

    // softmax sum
    float sum = 0.f;
    for (int k = t; k < K; k += TPB) sum += expf(pi_l[k] - mx);
    sred[t] = sum; __syncthreads();
    for (int s = TPB / 2; s > 0; s >>= 1) {
        if (t < s) sred[t] += sred[t + s];
        __syncthreads();
    }
    float tot = sred[0]; __syncthreads();

    // params + min sigma
    float smin = CUDART_INF_F;
    if (kok) {
        for (int k = t; k < K; k += TPB) {
            float pi   = expf(pi_l[k] - mx) / tot;
            float l    = lv[k];
            float sig  = expf(0.5f * l);
            smin = fminf(smin, sig);
            float coef = pi * 0.39894228040143267794f * expf(-0.5f * l);
            float s2   = -0.5f * expf(-l) * 1.44269504088896340736f;
            float b    = log2f(fmaxf(coef, 1e-38f));
            sp[k] = make_float4(mu[k], s2, b, 0.f);
        }
    }
    sred[t] = smin; __syncthreads();
    for (int s = TPB / 2; s > 0; s >>= 1) {
        if (t < s) sred[t] = fminf(sred[t], sred[t + s]);
        __syncthreads();
    }
    smin = sred[0];
    __syncthreads();

    if (blockIdx.x == 0) {
        if (kok) for (int k = t; k < K; k += TPB) g_params[k] = sp[k];
        if (t == 0) {
            // cubic-interp error ~ 0.026*(h/sigma)^4 rel; sigma >= 3.5h -> <2e-4
            g_interp = (kok && smin >= 3.5f * HSTEP) ? 1 : 0;
            g_mx = mx; g_tot = tot;
        }
    }
    if (!kok) return;

    // Evaluate table grid point p = gt - 1, p in [-1, MI+1]
    int gt = blockIdx.x * TPB + t;
    if (gt > MI + 2) return;
    int p = gt - 1;
    float x = LOF + (float)p * HSTEP;
    float acc = 0.f;
    for (int k = 0; k < K; k++) {
        float4 pp = sp[k];
        float d = x - pp.x;
        acc += ex2(fmaf(d * d, pp.y, pp.z));
    }
    g_y[gt] = acc;
}

// ---------------------------------------------------------------------------
// Convert y-stencils to per-cell cubic coefficients (exact Lagrange cubic).
// p(f) = c0 + f*(c1 + f*(c2 + f*c3)), f in [0,1) local coordinate of cell i.
// ---------------------------------------------------------------------------
__global__ void coef_kernel() {
    int i = blockIdx.x * blockDim.x + threadIdx.x;
    if (i >= MI) return;
    float ym = g_y[i];       // y[i-1]
    float y0 = g_y[i + 1];   // y[i]
    float y1 = g_y[i + 2];   // y[i+1]
    float y2 = g_y[i + 3];   // y[i+2]
    float c0 = y0;
    float c1 = -0.333333333f * ym - 0.5f * y0 + y1 - 0.166666667f * y2;
    float c2 = 0.5f * (ym + y1) - y0;
    float c3 = 0.5f * (y0 - y1) + 0.166666667f * (y2 - ym);
    g_coef[i] = make_float4(c0, c1, c2, c3);
}

// ---------------------------------------------------------------------------
// Fallback direct evaluations (cold paths)
// ---------------------------------------------------------------------------
__device__ __noinline__ float direct_eval(float x, int K) {
    float acc = 0.f;
    for (int k = 0; k < K; k++) {
        float4 p = g_params[k];
        float d = x - p.x;
        acc += ex2(fmaf(d * d, p.y, p.z));
    }
    return acc;
}

__device__ __noinline__ float direct_eval_raw(float x, const float* pi_l,
                                              const float* mu, const float* lv, int K) {
    float mx = g_mx, tot = g_tot;
    float acc = 0.f;
    for (int k = 0; k < K; k++) {
        float pi   = expf(pi_l[k] - mx) / tot;
        float l    = lv[k];
        float coef = pi * 0.39894228040143267794f * expf(-0.5f * l);
        float d    = x - mu[k];
        acc += coef * expf(-0.5f * d * d * expf(-l));
    }
    return acc;
}

// ---------------------------------------------------------------------------
// Hot eval: index + one LDS.128 + Horner. Clamp exact over table domain ⊇ [0,1].
// ---------------------------------------------------------------------------
__device__ __forceinline__ float interp1(float x, const float4* __restrict__ stab) {
    float t = fmaf(x, INVH, TT0);
    int i = __float2int_rz(t);
    i = min(max(i, 0), MI - 1);
    float f = t - (float)i;
    float4 c = stab[i];
    return fmaf(f, fmaf(f, fmaf(f, c.w, c.z), c.y), c.x);
}

__device__ __forceinline__ float4 interp4(float4 z, const float4* __restrict__ stab) {
    float4 r;
    r.x = interp1(z.x, stab);
    r.y = interp1(z.y, stab);
    r.z = interp1(z.z, stab);
    r.w = interp1(z.w, stab);
    return r;
}

__global__ __launch_bounds__(TPB, 6)
void interp_kernel(const float* __restrict__ mz,
                   float* __restrict__ out,
                   int n, int K,
                   const float* __restrict__ pi_l,
                   const float* __restrict__ mu,
                   const float* __restrict__ lv) {
    __shared__ float4 stab[MI];          // 16 KB
    int mode = g_interp;                 // uniform across grid
    if (mode) {
        for (int i = threadIdx.x; i < MI; i += TPB)
            stab[i] = g_coef[i];
    }
    __syncthreads();

    int gtid = blockIdx.x * TPB + threadIdx.x;
    int gsz  = gridDim.x * TPB;

    if (mode) {
        int n4 = n >> 2;
        const float4* mz4 = (const float4*)mz;
        float4* out4 = (float4*)out;

        // Batched main loop: 4 front-issued LDG.128 per thread (MLP=4).
        int i = gtid;
        for (; i + 3 * gsz < n4; i += 4 * gsz) {
            float4 z0 = mz4[i];
            float4 z1 = mz4[i + gsz];
            float4 z2 = mz4[i + 2 * gsz];
            float4 z3 = mz4[i + 3 * gsz];
            out4[i]           = interp4(z0, stab);
            out4[i + gsz]     = interp4(z1, stab);
            out4[i + 2 * gsz] = interp4(z2, stab);
            out4[i + 3 * gsz] = interp4(z3, stab);
        }
        for (; i < n4; i += gsz) {
            out4[i] = interp4(mz4[i], stab);
        }
        int rem = n & 3;
        if (gtid < rem) {
            int j = (n4 << 2) + gtid;
            out[j] = interp1(mz[j], stab);
        }
    } else if (K <= KMAX) {
        for (int i = gtid; i < n; i += gsz)
            out[i] = direct_eval(mz[i], K);
    } else {
        for (int i = gtid; i < n; i += gsz)
            out[i] = direct_eval_raw(mz[i], pi_l, mu, lv, K);
    }
}

// ---------------------------------------------------------------------------
// Inputs (metadata order): mz [N], pi_l [K], mu [K], lv [K]. Output: prob [N] f32.
// ---------------------------------------------------------------------------
extern "C" void kernel_launch(void* const* d_in, const int* in_sizes, int n_in,
                              void* d_out, int out_size) {
    const float* mz   = (const float*)d_in[0];
    const float* pi_l = (const float*)d_in[1];
    const float* mu   = (const float*)d_in[2];
    const float* lv   = (const float*)d_in[3];
    float* out = (float*)d_out;
    int n = in_sizes[0];
    int K = in_sizes[1];

    int blocks_b = (MI + 3 + TPB - 1) / TPB;   // 5
    build_kernel<<<blocks_b, TPB>>>(pi_l, mu, lv, K);
    coef_kernel<<<(MI + TPB - 1) / TPB, TPB>>>();

    int blocks = 148 * 6;                      // one resident wave at 6 CTA/SM
    int need = (n / 4 + TPB - 1) / TPB;
    if (need < 1) need = 1;
    if (blocks > need) blocks = need;
    interp_kernel<<<blocks, TPB>>>(mz, out, n, K, pi_l, mu, lv);
}

// round 6
// speedup vs baseline: 1.2882x; 1.2882x over previous
#include <cuda_runtime.h>
#include <math_constants.h>

#define TPB   256
#define MI    1024                     // interpolation cells
#define KMAX  1024
#define LOF   (-0.015625f)             // table domain start
#define HSTEP (33.0f/32768.0f)         // cell width h (exact in fp32)
#define INVH  (32768.0f/33.0f)         // 1/h
#define TT0   (512.0f/33.0f)           // -LOF/h
#define BBLD  128                      // builder blocks (8 warps each -> 1024 warps)

// Device scratch (no allocations allowed)
__device__ float4 g_params[KMAX];      // {mu, s=-0.5*inv_var*log2e, b=log2(coef), 0}
__device__ float4 g_coef[MI];          // per-cell cubic {c0,c1,c2,c3} in local f
__device__ int    g_interp;            // 1 -> interpolation valid
__device__ float  g_mx, g_tot;         // softmax stats (K>KMAX ultra-fallback)

__device__ __forceinline__ float ex2(float a) {
    float r;
    asm("ex2.approx.f32 %0, %1;" : "=f"(r) : "f"(a));
    return r;
}

__device__ __forceinline__ float wred_max(float v) {
#pragma unroll
    for (int o = 16; o; o >>= 1) v = fmaxf(v, __shfl_xor_sync(0xffffffffu, v, o));
    return v;
}
__device__ __forceinline__ float wred_min(float v) {
#pragma unroll
    for (int o = 16; o; o >>= 1) v = fminf(v, __shfl_xor_sync(0xffffffffu, v, o));
    return v;
}
__device__ __forceinline__ float wred_sum(float v) {
#pragma unroll
    for (int o = 16; o; o >>= 1) v += __shfl_xor_sync(0xffffffffu, v, o);
    return v;
}

// ---------------------------------------------------------------------------
// Fused builder: per-block redundant softmax+params (warp-shuffle reductions),
// then ONE WARP PER CELL computes the 4-point stencil exactly (lanes split K)
// and emits the cell's Horner coefficients. 2 launches total in the pipeline.
// ---------------------------------------------------------------------------
__global__ __launch_bounds__(TPB)
void build_fused(const float* __restrict__ pi_l,
                 const float* __restrict__ mu,
                 const float* __restrict__ lv, int K) {
    __shared__ float4 sp[KMAX];        // 16 KB params
    __shared__ float  sred[8];
    int t   = threadIdx.x;
    int wid = t >> 5, lid = t & 31;
    int kok = (K <= KMAX);

    // ---- softmax max ----
    float m = -CUDART_INF_F;
    for (int k = t; k < K; k += TPB) m = fmaxf(m, pi_l[k]);
    m = wred_max(m);
    if (lid == 0) sred[wid] = m;
    __syncthreads();
    float mx = fmaxf(fmaxf(fmaxf(sred[0], sred[1]), fmaxf(sred[2], sred[3])),
                     fmaxf(fmaxf(sred[4], sred[5]), fmaxf(sred[6], sred[7])));
    __syncthreads();

    // ---- softmax sum ----
    float sum = 0.f;
    for (int k = t; k < K; k += TPB) sum += expf(pi_l[k] - mx);
    sum = wred_sum(sum);
    if (lid == 0) sred[wid] = sum;
    __syncthreads();
    float tot = sred[0] + sred[1] + sred[2] + sred[3]
              + sred[4] + sred[5] + sred[6] + sred[7];
    __syncthreads();

    // ---- params + min sigma ----
    float smin = CUDART_INF_F;
    if (kok) {
        for (int k = t; k < K; k += TPB) {
            float pi   = expf(pi_l[k] - mx) / tot;
            float l    = lv[k];
            smin = fminf(smin, expf(0.5f * l));
            float coef = pi * 0.39894228040143267794f * expf(-0.5f * l);
            float s2   = -0.5f * expf(-l) * 1.44269504088896340736f;
            float b    = log2f(fmaxf(coef, 1e-38f));
            sp[k] = make_float4(mu[k], s2, b, 0.f);
        }
    }
    smin = wred_min(smin);
    if (lid == 0) sred[wid] = smin;
    __syncthreads();
    smin = fminf(fminf(fminf(sred[0], sred[1]), fminf(sred[2], sred[3])),
                 fminf(fminf(sred[4], sred[5]), fminf(sred[6], sred[7])));

    if (blockIdx.x == 0) {
        if (kok) for (int k = t; k < K; k += TPB) g_params[k] = sp[k];
        if (t == 0) {
            // cubic-interp error ~ 0.026*(h/sigma)^4 rel; sigma >= 3.5h -> <2e-4
            g_interp = (kok && smin >= 3.5f * HSTEP) ? 1 : 0;
            g_mx = mx; g_tot = tot;
        }
    }
    if (!kok) return;

    // ---- one warp per cell: 4 stencil points, lanes split K ----
    int warps_total = gridDim.x * (TPB >> 5);
    for (int cell = blockIdx.x * (TPB >> 5) + wid; cell < MI; cell += warps_total) {
        float x0 = LOF + (float)(cell - 1) * HSTEP;   // y[cell-1]
        float x1 = x0 + HSTEP;                        // y[cell]
        float x2 = x1 + HSTEP;                        // y[cell+1]
        float x3 = x2 + HSTEP;                        // y[cell+2]
        float a0 = 0.f, a1 = 0.f, a2 = 0.f, a3 = 0.f;
        for (int k = lid; k < K; k += 32) {
            float4 pp = sp[k];
            float d0 = x0 - pp.x;
            float d1 = x1 - pp.x;
            float d2 = x2 - pp.x;
            float d3 = x3 - pp.x;
            a0 += ex2(fmaf(d0 * d0, pp.y, pp.z));
            a1 += ex2(fmaf(d1 * d1, pp.y, pp.z));
            a2 += ex2(fmaf(d2 * d2, pp.y, pp.z));
            a3 += ex2(fmaf(d3 * d3, pp.y, pp.z));
        }
        a0 = wred_sum(a0);
        a1 = wred_sum(a1);
        a2 = wred_sum(a2);
        a3 = wred_sum(a3);
        if (lid == 0) {
            float ym = a0, y0 = a1, y1 = a2, y2 = a3;
            float c0 = y0;
            float c1 = -0.333333333f * ym - 0.5f * y0 + y1 - 0.166666667f * y2;
            float c2 = 0.5f * (ym + y1) - y0;
            float c3 = 0.5f * (y0 - y1) + 0.166666667f * (y2 - ym);
            g_coef[cell] = make_float4(c0, c1, c2, c3);
        }
    }
}

// ---------------------------------------------------------------------------
// Fallback direct evaluations (cold paths)
// ---------------------------------------------------------------------------
__device__ __noinline__ float direct_eval(float x, int K) {
    float acc = 0.f;
    for (int k = 0; k < K; k++) {
        float4 p = g_params[k];
        float d = x - p.x;
        acc += ex2(fmaf(d * d, p.y, p.z));
    }
    return acc;
}

__device__ __noinline__ float direct_eval_raw(float x, const float* pi_l,
                                              const float* mu, const float* lv, int K) {
    float mx = g_mx, tot = g_tot;
    float acc = 0.f;
    for (int k = 0; k < K; k++) {
        float pi   = expf(pi_l[k] - mx) / tot;
        float l    = lv[k];
        float coef = pi * 0.39894228040143267794f * expf(-0.5f * l);
        float d    = x - mu[k];
        acc += coef * expf(-0.5f * d * d * expf(-l));
    }
    return acc;
}

// ---------------------------------------------------------------------------
// Hot eval: index + one LDS.128 + Horner. Clamp exact over table domain ⊇ [0,1].
// ---------------------------------------------------------------------------
__device__ __forceinline__ float interp1(float x, const float4* __restrict__ stab) {
    float t = fmaf(x, INVH, TT0);
    int i = __float2int_rz(t);
    i = min(max(i, 0), MI - 1);
    float f = t - (float)i;
    float4 c = stab[i];
    return fmaf(f, fmaf(f, fmaf(f, c.w, c.z), c.y), c.x);
}

__device__ __forceinline__ float4 interp4(float4 z, const float4* __restrict__ stab) {
    float4 r;
    r.x = interp1(z.x, stab);
    r.y = interp1(z.y, stab);
    r.z = interp1(z.z, stab);
    r.w = interp1(z.w, stab);
    return r;
}

__global__ __launch_bounds__(TPB, 6)
void interp_kernel(const float* __restrict__ mz,
                   float* __restrict__ out,
                   int n, int K,
                   const float* __restrict__ pi_l,
                   const float* __restrict__ mu,
                   const float* __restrict__ lv) {
    __shared__ float4 stab[MI];          // 16 KB
    int mode = g_interp;                 // uniform across grid
    if (mode) {
        for (int i = threadIdx.x; i < MI; i += TPB)
            stab[i] = g_coef[i];
    }
    __syncthreads();

    int gtid = blockIdx.x * TPB + threadIdx.x;
    int gsz  = gridDim.x * TPB;

    if (mode) {
        int n4 = n >> 2;
        const float4* mz4 = (const float4*)mz;
        float4* out4 = (float4*)out;

        // Batched main loop: 4 front-issued LDG.128 per thread (MLP=4).
        int i = gtid;
        for (; i + 3 * gsz < n4; i += 4 * gsz) {
            float4 z0 = mz4[i];
            float4 z1 = mz4[i + gsz];
            float4 z2 = mz4[i + 2 * gsz];
            float4 z3 = mz4[i + 3 * gsz];
            out4[i]           = interp4(z0, stab);
            out4[i + gsz]     = interp4(z1, stab);
            out4[i + 2 * gsz] = interp4(z2, stab);
            out4[i + 3 * gsz] = interp4(z3, stab);
        }
        for (; i < n4; i += gsz) {
            out4[i] = interp4(mz4[i], stab);
        }
        int rem = n & 3;
        if (gtid < rem) {
            int j = (n4 << 2) + gtid;
            out[j] = interp1(mz[j], stab);
        }
    } else if (K <= KMAX) {
        for (int i = gtid; i < n; i += gsz)
            out[i] = direct_eval(mz[i], K);
    } else {
        for (int i = gtid; i < n; i += gsz)
            out[i] = direct_eval_raw(mz[i], pi_l, mu, lv, K);
    }
}

// ---------------------------------------------------------------------------
// Inputs (metadata order): mz [N], pi_l [K], mu [K], lv [K]. Output: prob [N] f32.
// ---------------------------------------------------------------------------
extern "C" void kernel_launch(void* const* d_in, const int* in_sizes, int n_in,
                              void* d_out, int out_size) {
    const float* mz   = (const float*)d_in[0];
    const float* pi_l = (const float*)d_in[1];
    const float* mu   = (const float*)d_in[2];
    const float* lv   = (const float*)d_in[3];
    float* out = (float*)d_out;
    int n = in_sizes[0];
    int K = in_sizes[1];

    build_fused<<<BBLD, TPB>>>(pi_l, mu, lv, K);

    int blocks = 148 * 6;                      // one resident wave at 6 CTA/SM
    int need = (n / 4 + TPB - 1) / TPB;
    if (need < 1) need = 1;
    if (blocks > need) blocks = need;
    interp_kernel<<<blocks, TPB>>>(mz, out, n, K, pi_l, mu, lv);
}

// round 7
// speedup vs baseline: 1.2909x; 1.0022x over previous
#include <cuda_runtime.h>
#include <cuda_fp16.h>
#include <math_constants.h>

#define TPB   256
#define MI    2048                     // interpolation cells
#define KMAX  1024
#define LOF   (-0.015625f)             // table domain start
#define HSTEP (33.0f/65536.0f)         // cell width h (exact in fp32)
#define INVH  (65536.0f/33.0f)         // 1/h
#define TT0   (1024.0f/33.0f)          // -LOF/h
#define BBLD  148                      // builder blocks

// Device scratch (no allocations allowed)
__device__ float4 g_params[KMAX];      // {mu, s=-0.5*inv_var*log2e, b=log2(coef), 0}
__device__ float2 g_coef[MI];          // per-cell quadratic {c0 f32, (c1,c2) half2}
__device__ int    g_interp;            // 1 -> interpolation valid
__device__ float  g_mx, g_tot;         // softmax stats (K>KMAX ultra-fallback)

__device__ __forceinline__ float ex2(float a) {
    float r;
    asm("ex2.approx.f32 %0, %1;" : "=f"(r) : "f"(a));
    return r;
}

__device__ __forceinline__ float wred_max(float v) {
#pragma unroll
    for (int o = 16; o; o >>= 1) v = fmaxf(v, __shfl_xor_sync(0xffffffffu, v, o));
    return v;
}
__device__ __forceinline__ float wred_min(float v) {
#pragma unroll
    for (int o = 16; o; o >>= 1) v = fminf(v, __shfl_xor_sync(0xffffffffu, v, o));
    return v;
}
__device__ __forceinline__ float wred_sum(float v) {
#pragma unroll
    for (int o = 16; o; o >>= 1) v += __shfl_xor_sync(0xffffffffu, v, o);
    return v;
}

// ---------------------------------------------------------------------------
// Fused builder: per-block redundant softmax+params (warp-shuffle reductions),
// then ONE WARP PER CELL computes the 3-point stencil exactly (lanes split K)
// and emits packed quadratic coefficients for the cell.
// Quadratic through f=0,1,2: c0=y0, c1=-1.5y0+2y1-0.5y2, c2=0.5(y0-2y1+y2).
// ---------------------------------------------------------------------------
__global__ __launch_bounds__(TPB)
void build_fused(const float* __restrict__ pi_l,
                 const float* __restrict__ mu,
                 const float* __restrict__ lv, int K) {
    __shared__ float4 sp[KMAX];        // 16 KB params
    __shared__ float  sred[8];
    int t   = threadIdx.x;
    int wid = t >> 5, lid = t & 31;
    int kok = (K <= KMAX);

    // ---- softmax max ----
    float m = -CUDART_INF_F;
    for (int k = t; k < K; k += TPB) m = fmaxf(m, pi_l[k]);
    m = wred_max(m);
    if (lid == 0) sred[wid] = m;
    __syncthreads();
    float mx = fmaxf(fmaxf(fmaxf(sred[0], sred[1]), fmaxf(sred[2], sred[3])),
                     fmaxf(fmaxf(sred[4], sred[5]), fmaxf(sred[6], sred[7])));
    __syncthreads();

    // ---- softmax sum ----
    float sum = 0.f;
    for (int k = t; k < K; k += TPB) sum += expf(pi_l[k] - mx);
    sum = wred_sum(sum);
    if (lid == 0) sred[wid] = sum;
    __syncthreads();
    float tot = sred[0] + sred[1] + sred[2] + sred[3]
              + sred[4] + sred[5] + sred[6] + sred[7];
    __syncthreads();

    // ---- params + min sigma ----
    float smin = CUDART_INF_F;
    if (kok) {
        for (int k = t; k < K; k += TPB) {
            float pi   = expf(pi_l[k] - mx) / tot;
            float l    = lv[k];
            smin = fminf(smin, expf(0.5f * l));
            float coef = pi * 0.39894228040143267794f * expf(-0.5f * l);
            float s2   = -0.5f * expf(-l) * 1.44269504088896340736f;
            float b    = log2f(fmaxf(coef, 1e-38f));
            sp[k] = make_float4(mu[k], s2, b, 0.f);
        }
    }
    smin = wred_min(smin);
    if (lid == 0) sred[wid] = smin;
    __syncthreads();
    smin = fminf(fminf(fminf(sred[0], sred[1]), fminf(sred[2], sred[3])),
                 fminf(fminf(sred[4], sred[5]), fminf(sred[6], sred[7])));

    if (blockIdx.x == 0) {
        if (kok) for (int k = t; k < K; k += TPB) g_params[k] = sp[k];
        if (t == 0) {
            // quadratic-interp err ~ 0.08*(h/sigma)^3 rel; sigma >= 5.5h -> <6e-4
            g_interp = (kok && smin >= 5.5f * HSTEP) ? 1 : 0;
            g_mx = mx; g_tot = tot;
        }
    }
    if (!kok) return;

    // ---- one warp per cell: 3 stencil points, lanes split K ----
    int warps_total = gridDim.x * (TPB >> 5);
    for (int cell = blockIdx.x * (TPB >> 5) + wid; cell < MI; cell += warps_total) {
        float x0 = LOF + (float)cell * HSTEP;   // y[cell]
        float x1 = x0 + HSTEP;                  // y[cell+1]
        float x2 = x1 + HSTEP;                  // y[cell+2]
        float a0 = 0.f, a1 = 0.f, a2 = 0.f;
        for (int k = lid; k < K; k += 32) {
            float4 pp = sp[k];
            float d0 = x0 - pp.x;
            float d1 = x1 - pp.x;
            float d2 = x2 - pp.x;
            a0 += ex2(fmaf(d0 * d0, pp.y, pp.z));
            a1 += ex2(fmaf(d1 * d1, pp.y, pp.z));
            a2 += ex2(fmaf(d2 * d2, pp.y, pp.z));
        }
        a0 = wred_sum(a0);
        a1 = wred_sum(a1);
        a2 = wred_sum(a2);
        if (lid == 0) {
            float c0 = a0;
            float c1 = fmaf(-1.5f, a0, fmaf(2.0f, a1, -0.5f * a2));
            float c2 = 0.5f * (a0 - 2.0f * a1 + a2);
            __half2 h12 = __floats2half2_rn(c1, c2);
            float2 e;
            e.x = c0;
            e.y = __uint_as_float(*reinterpret_cast<unsigned int*>(&h12));
            g_coef[cell] = e;
        }
    }
}

// ---------------------------------------------------------------------------
// Fallback direct evaluations (cold paths)
// ---------------------------------------------------------------------------
__device__ __noinline__ float direct_eval(float x, int K) {
    float acc = 0.f;
    for (int k = 0; k < K; k++) {
        float4 p = g_params[k];
        float d = x - p.x;
        acc += ex2(fmaf(d * d, p.y, p.z));
    }
    return acc;
}

__device__ __noinline__ float direct_eval_raw(float x, const float* pi_l,
                                              const float* mu, const float* lv, int K) {
    float mx = g_mx, tot = g_tot;
    float acc = 0.f;
    for (int k = 0; k < K; k++) {
        float pi   = expf(pi_l[k] - mx) / tot;
        float l    = lv[k];
        float coef = pi * 0.39894228040143267794f * expf(-0.5f * l);
        float d    = x - mu[k];
        acc += coef * expf(-0.5f * d * d * expf(-l));
    }
    return acc;
}

// ---------------------------------------------------------------------------
// Hot eval: index + one LDS.64 + 2-FMA Horner (c1,c2 in half2).
// Float-side clamp keeps i in [0, MI-1] for any finite x.
// ---------------------------------------------------------------------------
__device__ __forceinline__ float interp1(float x, const float2* __restrict__ stab) {
    float t = fmaf(x, INVH, TT0);
    t = fminf(fmaxf(t, 0.0f), (float)MI - 0.5f);
    int i = __float2int_rz(t);
    float f = t - (float)i;
    float2 e = stab[i];
    unsigned int u = __float_as_uint(e.y);
    __half2 h12 = *reinterpret_cast<__half2*>(&u);
    float2 c = __half22float2(h12);
    return fmaf(f, fmaf(f, c.y, c.x), e.x);
}

__device__ __forceinline__ float4 interp4(float4 z, const float2* __restrict__ stab) {
    float4 r;
    r.x = interp1(z.x, stab);
    r.y = interp1(z.y, stab);
    r.z = interp1(z.z, stab);
    r.w = interp1(z.w, stab);
    return r;
}

__global__ __launch_bounds__(TPB, 6)
void interp_kernel(const float* __restrict__ mz,
                   float* __restrict__ out,
                   int n, int K,
                   const float* __restrict__ pi_l,
                   const float* __restrict__ mu,
                   const float* __restrict__ lv) {
    __shared__ float2 stab[MI];          // 16 KB
    int mode = g_interp;                 // uniform across grid
    if (mode) {
#pragma unroll 4
        for (int i = threadIdx.x; i < MI; i += TPB)
            stab[i] = g_coef[i];
    }
    __syncthreads();

    int gtid = blockIdx.x * TPB + threadIdx.x;
    int gsz  = gridDim.x * TPB;

    if (mode) {
        int n4 = n >> 2;
        const float4* mz4 = (const float4*)mz;
        float4* out4 = (float4*)out;

        // Batched main loop: 4 front-issued LDG.128 per thread (MLP=4).
        int i = gtid;
        for (; i + 3 * gsz < n4; i += 4 * gsz) {
            float4 z0 = mz4[i];
            float4 z1 = mz4[i + gsz];
            float4 z2 = mz4[i + 2 * gsz];
            float4 z3 = mz4[i + 3 * gsz];
            out4[i]           = interp4(z0, stab);
            out4[i + gsz]     = interp4(z1, stab);
            out4[i + 2 * gsz] = interp4(z2, stab);
            out4[i + 3 * gsz] = interp4(z3, stab);
        }
        for (; i < n4; i += gsz) {
            out4[i] = interp4(mz4[i], stab);
        }
        int rem = n & 3;
        if (gtid < rem) {
            int j = (n4 << 2) + gtid;
            out[j] = interp1(mz[j], stab);
        }
    } else if (K <= KMAX) {
        for (int i = gtid; i < n; i += gsz)
            out[i] = direct_eval(mz[i], K);
    } else {
        for (int i = gtid; i < n; i += gsz)
            out[i] = direct_eval_raw(mz[i], pi_l, mu, lv, K);
    }
}

// ---------------------------------------------------------------------------
// Inputs (metadata order): mz [N], pi_l [K], mu [K], lv [K]. Output: prob [N] f32.
// ---------------------------------------------------------------------------
extern "C" void kernel_launch(void* const* d_in, const int* in_sizes, int n_in,
                              void* d_out, int out_size) {
    const float* mz   = (const float*)d_in[0];
    const float* pi_l = (const float*)d_in[1];
    const float* mu   = (const float*)d_in[2];
    const float* lv   = (const float*)d_in[3];
    float* out = (float*)d_out;
    int n = in_sizes[0];
    int K = in_sizes[1];

    build_fused<<<BBLD, TPB>>>(pi_l, mu, lv, K);

    int blocks = 148 * 6;                      // one resident wave at 6 CTA/SM
    int need = (n / 4 + TPB - 1) / TPB;
    if (need < 1) need = 1;
    if (blocks > need) blocks = need;
    interp_kernel<<<blocks, TPB>>>(mz, out, n, K, pi_l, mu, lv);
}